// round 8
// baseline (speedup 1.0000x reference)
#include <cuda_runtime.h>
#include <math.h>

// ---------------- problem constants ----------------
#define B_ 16
#define T_ 2048
#define H_ 1024
#define H4 (H_ / 4)      // 256 float4 per row
#define BT 32            // timesteps per block in alphas kernel (grid = 1024)
#define RPB 8            // output rows per gather block

// ---------------- device scratch (no allocations allowed) ----------------
__device__ float g_alphas[B_ * T_];
__device__ float g_dist[B_ * T_];
__device__ float g_rem[B_ * T_];
__device__ int   g_fire_t[B_ * T_];
__device__ int   g_nf[B_];
__device__ float g_dummy_len[B_];
__device__ float g_dummy_fires[B_ * T_];

// ---------------- kernel A: alphas = sigmoid(lin(relu(dwconv3(x)+x))) ------
__device__ __forceinline__ float part1(float xm, float x0, float xp,
                                       float w0, float w1, float w2,
                                       float cb, float lw) {
    float v = fmaf(w0, xm, fmaf(w1, x0, fmaf(w2, xp, cb)));
    v += x0;                 // residual
    v = fmaxf(v, 0.0f);      // relu
    return lw * v;
}

__global__ __launch_bounds__(256, 5) void alphas_kernel(
    const float* __restrict__ hidden, const float* __restrict__ conv_w,
    const float* __restrict__ conv_b, const float* __restrict__ lin_w,
    const float* __restrict__ lin_b)
{
    const int b = blockIdx.y;
    const int tstart = blockIdx.x * BT;
    const int tid = threadIdx.x;
    const int lane = tid & 31;
    const int warp = tid >> 5;

    __shared__ float wpart[4][8];   // [t within group][warp]

    const int h0 = tid * 4;
    float w0[4], w1[4], w2[4], cb[4], lw[4];
#pragma unroll
    for (int j = 0; j < 4; j++) {
        w0[j] = conv_w[(h0 + j) * 3 + 0];
        w1[j] = conv_w[(h0 + j) * 3 + 1];
        w2[j] = conv_w[(h0 + j) * 3 + 2];
        cb[j] = conv_b[h0 + j];
        lw[j] = lin_w[h0 + j];
    }
    const float lb = lin_b[0];

    const float4* Hb = (const float4*)hidden + (size_t)b * T_ * H4;
    const float4 z4 = make_float4(0.f, 0.f, 0.f, 0.f);

    float4 xm = (tstart > 0) ? Hb[(size_t)(tstart - 1) * H4 + tid] : z4;
    float4 x0 = Hb[(size_t)tstart * H4 + tid];

    for (int c = 0; c < BT / 4; ++c) {
        const int t0 = tstart + c * 4;
        float4 xA = Hb[(size_t)(t0 + 1) * H4 + tid];
        float4 xB = Hb[(size_t)(t0 + 2) * H4 + tid];
        float4 xC = Hb[(size_t)(t0 + 3) * H4 + tid];
        float4 xD = (t0 + 4 < T_) ? Hb[(size_t)(t0 + 4) * H4 + tid] : z4;

        float s[4];
        {
            const float4* P[6] = { &xm, &x0, &xA, &xB, &xC, &xD };
#pragma unroll
            for (int i = 0; i < 4; i++) {
                const float4 a = *P[i], m = *P[i + 1], p = *P[i + 2];
                float acc;
                acc  = part1(a.x, m.x, p.x, w0[0], w1[0], w2[0], cb[0], lw[0]);
                acc += part1(a.y, m.y, p.y, w0[1], w1[1], w2[1], cb[1], lw[1]);
                acc += part1(a.z, m.z, p.z, w0[2], w1[2], w2[2], cb[2], lw[2]);
                acc += part1(a.w, m.w, p.w, w0[3], w1[3], w2[3], cb[3], lw[3]);
                s[i] = acc;
            }
        }
#pragma unroll
        for (int i = 0; i < 4; i++) {
#pragma unroll
            for (int off = 16; off; off >>= 1)
                s[i] += __shfl_xor_sync(0xffffffffu, s[i], off);
        }
        if (lane == 0) {
#pragma unroll
            for (int i = 0; i < 4; i++) wpart[i][warp] = s[i];
        }
        __syncthreads();
        if (tid < 4) {
            float tot = lb;
#pragma unroll
            for (int w = 0; w < 8; w++) tot += wpart[tid][w];
            g_alphas[b * T_ + t0 + tid] = 1.0f / (1.0f + expf(-tot));
        }
        __syncthreads();
        xm = xC;
        x0 = xD;
    }
}

// ---------------- kernel S: exact sequential integrate-and-fire scan -------
__global__ __launch_bounds__(128) void scan_kernel(float* __restrict__ out_fires,
                                                   float* __restrict__ out_len)
{
    const int b = blockIdx.x;
    __shared__ float a_s[T_];
    __shared__ float fires_s[T_];
    __shared__ float dist_s[T_];
    __shared__ float rem_s[T_];
    __shared__ int   ft_s[T_];
    __shared__ int   s_nf;

    const float* ab = g_alphas + b * T_;
    for (int i = threadIdx.x; i < T_; i += blockDim.x) a_s[i] = ab[i];
    __syncthreads();

    if (threadIdx.x == 0) {
        float integ = 0.0f;
        int nf = 0;
        for (int t = 0; t < T_; t += 8) {
            float av[8];
#pragma unroll
            for (int j = 0; j < 8; j++) av[j] = a_s[t + j];
#pragma unroll
            for (int j = 0; j < 8; j++) {
                const float a = av[j];
                const float t1 = integ + a;        // fires value (pre-subtract)
                const float dist = 1.0f - integ;   // distribution completion
                const float t2 = t1 - 1.0f;        // exact on [1,2) (Sterbenz)
                const bool fire = (t1 >= 1.0f);
                fires_s[t + j] = t1;
                dist_s[t + j]  = dist;
                rem_s[t + j]   = a - dist;
                ft_s[nf] = t + j;                  // unconditional; kept iff fire
                nf += fire ? 1 : 0;
                integ = fire ? t2 : t1;
            }
        }
        s_nf = nf;
        g_nf[b] = nf;
        out_len[b] = integ + (float)nf;            // == fp-sum of alphas
    }
    __syncthreads();

    const int nf = s_nf;
    float* fires = out_fires + b * T_;
    const int base = b * T_;
    for (int i = threadIdx.x; i < T_; i += blockDim.x) {
        fires[i]         = fires_s[i];
        g_dist[base + i] = dist_s[i];
        g_rem[base + i]  = rem_s[i];
    }
    for (int i = threadIdx.x; i < nf; i += blockDim.x)
        g_fire_t[base + i] = ft_s[i];
}

// ---------------- kernel C: REVERSE-ORDER tile-batched gather --------------
// Blocks are remapped so the first-scheduled CTAs process (batch 15, highest
// t) — the portion of `hidden` most recently read by alphas and thus still
// L2-resident. Each block walks its t-range DESCENDING with front-batched
// tiles of 4 LDG.128. Per-row sums use a different (descending) accumulation
// order than the reference — fine under the 1e-3 rel-err gate; the fire
// pattern itself is exact.
__global__ __launch_bounds__(256) void gather_kernel(
    const float* __restrict__ hidden, float* __restrict__ out, int L)
{
    const int b = (B_ - 1) - blockIdx.y;                     // batch reversed
    const int r0 = (int)(gridDim.x - 1 - blockIdx.x) * RPB;  // rows reversed
    const int tid = threadIdx.x;

    __shared__ int   s_ft[RPB];
    __shared__ float s_dist[RPB];
    __shared__ float s_rem[RPB];
    __shared__ float s_remprev;
    __shared__ int   s_tprev;

    const int nf = g_nf[b];
    const int bT = b * T_;
    const int rlim = min(L, r0 + RPB);
    const int rend = min(nf, rlim);
    const int nr = rend - r0;               // real rows in this block

    if (tid < RPB && tid < nr) {
        const int ft = g_fire_t[bT + r0 + tid];
        s_ft[tid]   = ft;
        s_dist[tid] = g_dist[bT + ft];
        s_rem[tid]  = g_rem[bT + ft];
    }
    if (tid == 0) {
        if (r0 > 0 && nr > 0) {
            const int tp = g_fire_t[bT + r0 - 1];
            s_tprev = tp;
            s_remprev = g_rem[bT + tp];
        } else {
            s_tprev = -1;
            s_remprev = 0.0f;
        }
    }
    __syncthreads();

    const float4* Hb = (const float4*)hidden + (size_t)b * T_ * H4;
    float4* Ob = (float4*)out + (size_t)b * L * H4;

    // zero-fill padding rows first (these are the highest r -> written early)
    const float4 z4 = make_float4(0.f, 0.f, 0.f, 0.f);
    for (int r = r0 + max(nr, 0); r < rlim; ++r)
        Ob[(size_t)r * H4 + tid] = z4;

    if (nr > 0) {
        const int thi = s_ft[nr - 1];
        const int tlo = (s_tprev >= 0) ? s_tprev : 0;
        const float* Ab = g_alphas + bT;

        int j = nr - 1;                 // open (accumulating) local row
        // start row nr-1 at its own fire position
        float4 acc;
        {
            const float d = s_dist[j];
            const float4 h = __ldg(&Hb[(size_t)thi * H4 + tid]);
            acc.x = d * h.x; acc.y = d * h.y; acc.z = d * h.z; acc.w = d * h.w;
        }

        for (int t = thi - 1; t >= tlo; t -= 4) {
            const int i0 = t;
            const int i1 = max(t - 1, tlo);
            const int i2 = max(t - 2, tlo);
            const int i3 = max(t - 3, tlo);
            // front-batched tile loads (MLP_p1 = 4)
            const float4 h0 = __ldg(&Hb[(size_t)i0 * H4 + tid]);
            const float4 h1 = __ldg(&Hb[(size_t)i1 * H4 + tid]);
            const float4 h2 = __ldg(&Hb[(size_t)i2 * H4 + tid]);
            const float4 h3 = __ldg(&Hb[(size_t)i3 * H4 + tid]);
            const float a0 = __ldg(Ab + i0);
            const float a1 = __ldg(Ab + i1);
            const float a2 = __ldg(Ab + i2);
            const float a3 = __ldg(Ab + i3);
            const float4 hv[4] = { h0, h1, h2, h3 };
            const float  av[4] = { a0, a1, a2, a3 };
#pragma unroll
            for (int jj = 0; jj < 4; jj++) {
                const int tt = t - jj;
                if (tt < tlo) break;
                const float4 h = hv[jj];
                const int ev = (j >= 1) ? s_ft[j - 1] : s_tprev;
                if (tt == ev) {
                    // close open row j with the rem term of the fire below it
                    const float rm = (j >= 1) ? s_rem[j - 1] : s_remprev;
                    float4 o;
                    o.x = fmaf(rm, h.x, acc.x); o.y = fmaf(rm, h.y, acc.y);
                    o.z = fmaf(rm, h.z, acc.z); o.w = fmaf(rm, h.w, acc.w);
                    Ob[(size_t)(r0 + j) * H4 + tid] = o;
                    if (j >= 1) {       // start row j-1 at this fire
                        const float d = s_dist[j - 1];
                        acc.x = d * h.x; acc.y = d * h.y;
                        acc.z = d * h.z; acc.w = d * h.w;
                        --j;
                    } else {
                        j = -1;         // block fully emitted
                    }
                } else {
                    const float a = av[jj];
                    acc.x = fmaf(a, h.x, acc.x); acc.y = fmaf(a, h.y, acc.y);
                    acc.z = fmaf(a, h.z, acc.z); acc.w = fmaf(a, h.w, acc.w);
                }
            }
        }
        // global first row (no lower fire): emit after reaching t = 0
        if (j == 0 && s_tprev < 0)
            Ob[(size_t)(r0 + 0) * H4 + tid] = acc;
    }
}

// ---------------- launch ---------------------------------------------------
extern "C" void kernel_launch(void* const* d_in, const int* in_sizes, int n_in,
                              void* d_out, int out_size)
{
    const float* hidden = (const float*)d_in[0];
    const float* conv_w = (const float*)d_in[1];
    const float* conv_b = (const float*)d_in[2];
    const float* lin_w  = (const float*)d_in[3];
    const float* lin_b  = (const float*)d_in[4];

    float* out = (float*)d_out;

    // Output layout: tuple (cif_output[B,L,H], cif_length[B], fires[B,T])
    const long long fixed = (long long)B_ + (long long)B_ * T_;
    long long rem = (long long)out_size - fixed;
    int L;
    float* out_cif;
    float* out_len;
    float* out_fires;
    if (rem > 0 && rem % ((long long)B_ * H_) == 0) {
        L = (int)(rem / ((long long)B_ * H_));
        out_cif   = out;
        out_len   = out + (size_t)B_ * L * H_;
        out_fires = out_len + B_;
    } else {
        L = (int)((long long)out_size / ((long long)B_ * H_));
        out_cif = out;
        cudaGetSymbolAddress((void**)&out_len, g_dummy_len);
        cudaGetSymbolAddress((void**)&out_fires, g_dummy_fires);
    }

    alphas_kernel<<<dim3(T_ / BT, B_), 256>>>(hidden, conv_w, conv_b,
                                              lin_w, lin_b);
    scan_kernel<<<B_, 128>>>(out_fires, out_len);
    if (L > 0)
        gather_kernel<<<dim3((L + RPB - 1) / RPB, B_), 256>>>(hidden, out_cif, L);
}

// round 10
// speedup vs baseline: 1.1077x; 1.1077x over previous
#include <cuda_runtime.h>
#include <math.h>

// ---------------- problem constants ----------------
#define B_ 16
#define T_ 2048
#define H_ 1024
#define H4 (H_ / 4)      // 256 float4 per row
#define BT 32            // timesteps per alphas block
#define NCHUNK (T_ / BT) // 64 alphas blocks per batch
#define NA (B_ * NCHUNK) // 1024 alphas blocks total
#define RPB 8            // output rows per gather block

// ---------------- device scratch (no allocations allowed) ----------------
__device__ float g_alphas[B_ * T_];
__device__ float g_dist[B_ * T_];
__device__ float g_rem[B_ * T_];
__device__ int   g_fire_t[B_ * T_];
__device__ int   g_nf[B_];
__device__ int   g_cnt[B_];     // alphas completion tickets
__device__ int   g_sflag[B_];   // scan-done flags
__device__ float g_dummy_len[B_];
__device__ float g_dummy_fires[B_ * T_];

// ---------------- init: reset tickets/flags each call ----------------------
__global__ void init_kernel() {
    if (threadIdx.x < B_) { g_cnt[threadIdx.x] = 0; g_sflag[threadIdx.x] = 0; }
}

// ---------------- alphas math helper ----------------
__device__ __forceinline__ float part1(float xm, float x0, float xp,
                                       float w0, float w1, float w2,
                                       float cb, float lw) {
    float v = fmaf(w0, xm, fmaf(w1, x0, fmaf(w2, xp, cb)));
    v += x0;                 // residual
    v = fmaxf(v, 0.0f);      // relu
    return lw * v;
}

// ---------------- fused kernel ---------------------------------------------
// bids [0, NA)          : alphas, batch-major (b = bid/64). The LAST finisher
//                         of each batch (ticket) runs that batch's scan.
// bids [NA, NA+16*gblk) : gather, batch-major; waits on per-batch scan flag.
__global__ __launch_bounds__(256) void fused_kernel(
    const float* __restrict__ hidden, const float* __restrict__ conv_w,
    const float* __restrict__ conv_b, const float* __restrict__ lin_w,
    const float* __restrict__ lin_b,
    float* __restrict__ out_cif, float* __restrict__ out_len,
    float* __restrict__ out_fires, int L, int gblocks)
{
    // scan staging (idle for alphas/gather roles): 5*T_*4 = 40KB
    __shared__ float s_a[T_];
    __shared__ float s_f[T_];
    __shared__ float s_d[T_];
    __shared__ float s_r[T_];
    __shared__ int   s_t[T_];
    __shared__ int   s_misc[48];    // small int state (all roles)
    __shared__ float s_fmisc[48];   // small float state; alphas wpart = 32 floats

    const int bid = blockIdx.x;
    const int tid = threadIdx.x;

    if (bid < NA) {
        // ======================= ALPHAS (R6 body) =======================
        const int b = bid >> 6;             // batch-major: batch 0 first
        const int tstart = (bid & 63) * BT;
        const int lane = tid & 31;
        const int warp = tid >> 5;
        float (*wpart)[8] = (float (*)[8])s_fmisc;  // [4][8] = 32 floats (fits)

        const int h0 = tid * 4;
        float w0[4], w1[4], w2[4], cb[4], lw[4];
#pragma unroll
        for (int j = 0; j < 4; j++) {
            w0[j] = conv_w[(h0 + j) * 3 + 0];
            w1[j] = conv_w[(h0 + j) * 3 + 1];
            w2[j] = conv_w[(h0 + j) * 3 + 2];
            cb[j] = conv_b[h0 + j];
            lw[j] = lin_w[h0 + j];
        }
        const float lb = lin_b[0];

        const float4* Hb = (const float4*)hidden + (size_t)b * T_ * H4;
        const float4 z4 = make_float4(0.f, 0.f, 0.f, 0.f);

        float4 xm = (tstart > 0) ? Hb[(size_t)(tstart - 1) * H4 + tid] : z4;
        float4 x0 = Hb[(size_t)tstart * H4 + tid];

        for (int c = 0; c < BT / 4; ++c) {
            const int t0 = tstart + c * 4;
            float4 xA = Hb[(size_t)(t0 + 1) * H4 + tid];
            float4 xB = Hb[(size_t)(t0 + 2) * H4 + tid];
            float4 xC = Hb[(size_t)(t0 + 3) * H4 + tid];
            float4 xD = (t0 + 4 < T_) ? Hb[(size_t)(t0 + 4) * H4 + tid] : z4;

            float s[4];
            {
                const float4* P[6] = { &xm, &x0, &xA, &xB, &xC, &xD };
#pragma unroll
                for (int i = 0; i < 4; i++) {
                    const float4 a = *P[i], m = *P[i + 1], p = *P[i + 2];
                    float acc;
                    acc  = part1(a.x, m.x, p.x, w0[0], w1[0], w2[0], cb[0], lw[0]);
                    acc += part1(a.y, m.y, p.y, w0[1], w1[1], w2[1], cb[1], lw[1]);
                    acc += part1(a.z, m.z, p.z, w0[2], w1[2], w2[2], cb[2], lw[2]);
                    acc += part1(a.w, m.w, p.w, w0[3], w1[3], w2[3], cb[3], lw[3]);
                    s[i] = acc;
                }
            }
#pragma unroll
            for (int i = 0; i < 4; i++) {
#pragma unroll
                for (int off = 16; off; off >>= 1)
                    s[i] += __shfl_xor_sync(0xffffffffu, s[i], off);
            }
            if (lane == 0) {
#pragma unroll
                for (int i = 0; i < 4; i++) wpart[i][warp] = s[i];
            }
            __syncthreads();
            if (tid < 4) {
                float tot = lb;
#pragma unroll
                for (int w = 0; w < 8; w++) tot += wpart[tid][w];
                g_alphas[b * T_ + t0 + tid] = 1.0f / (1.0f + expf(-tot));
            }
            __syncthreads();
            xm = xC;
            x0 = xD;
        }

        // ---- ticket: last finisher of this batch runs the scan ----
        __threadfence();                       // release our alphas stores
        if (tid == 0)
            s_misc[0] = (atomicAdd(&g_cnt[b], 1) == NCHUNK - 1) ? 1 : 0;
        __syncthreads();
        if (s_misc[0] == 0) return;

        // ======================= SCAN (R6 body, __ldcg) =================
        const int bT = b * T_;
        {
            const float4* ap = (const float4*)(g_alphas + bT);
            for (int i = tid; i < T_ / 4; i += 256)
                ((float4*)s_a)[i] = __ldcg(ap + i);
        }
        __syncthreads();

        if (tid == 0) {
            float integ = 0.0f;
            int nf = 0;
            for (int t = 0; t < T_; t += 8) {
                float av[8];
#pragma unroll
                for (int j = 0; j < 8; j++) av[j] = s_a[t + j];
#pragma unroll
                for (int j = 0; j < 8; j++) {
                    const float a = av[j];
                    const float t1 = integ + a;      // fires (pre-subtract)
                    const float dist = 1.0f - integ; // distribution completion
                    const float t2 = t1 - 1.0f;      // exact on [1,2) (Sterbenz)
                    const bool fire = (t1 >= 1.0f);
                    s_f[t + j] = t1;
                    s_d[t + j] = dist;
                    s_r[t + j] = a - dist;
                    s_t[nf] = t + j;                 // kept iff fire
                    nf += fire ? 1 : 0;
                    integ = fire ? t2 : t1;
                }
            }
            s_misc[1] = nf;
            g_nf[b] = nf;
            out_len[b] = integ + (float)nf;          // == fp-sum of alphas
        }
        __syncthreads();

        const int nf = s_misc[1];
        for (int i = tid; i < T_; i += 256) {
            out_fires[bT + i] = s_f[i];
            g_dist[bT + i]    = s_d[i];
            g_rem[bT + i]     = s_r[i];
        }
        for (int i = tid; i < nf; i += 256)
            g_fire_t[bT + i] = s_t[i];
        __threadfence();                       // release scan results
        __syncthreads();
        if (tid == 0) atomicExch(&g_sflag[b], 1);
    } else {
        // ======================= GATHER (R6 body, __ldcg) ===============
        const int idx = bid - NA;
        const int b = idx / gblocks;           // batch-major
        const int r0 = (idx - b * gblocks) * RPB;

        if (tid == 0) {                        // wait for this batch's scan
            while (__ldcg(&g_sflag[b]) == 0) __nanosleep(128);
        }
        __syncthreads();
        __threadfence();

        int*   s_ft   = s_misc + 8;            // [RPB]
        float* s_dist = s_fmisc;               // [RPB]
        float* s_rem  = s_fmisc + RPB;         // [RPB]

        const int nf = __ldcg(&g_nf[b]);
        const int bT = b * T_;
        const int rlim = min(L, r0 + RPB);
        const int rend = min(nf, rlim);
        const int nr = rend - r0;

        if (tid < RPB && tid < nr) {
            const int ft = __ldcg(&g_fire_t[bT + r0 + tid]);
            s_ft[tid]   = ft;
            s_dist[tid] = __ldcg(&g_dist[bT + ft]);
            s_rem[tid]  = __ldcg(&g_rem[bT + ft]);
        }
        if (tid == 0) {
            if (r0 > 0 && nr > 0) {
                const int tp = __ldcg(&g_fire_t[bT + r0 - 1]);
                s_misc[1] = tp;
                s_fmisc[2 * RPB] = __ldcg(&g_rem[bT + tp]);
            } else {
                s_misc[1] = -1;
                s_fmisc[2 * RPB] = 0.0f;
            }
        }
        __syncthreads();
        const int   tprev   = s_misc[1];
        const float remprev = s_fmisc[2 * RPB];

        const float4* Hb = (const float4*)hidden + (size_t)b * T_ * H4;
        float4* Ob = (float4*)out_cif + (size_t)b * L * H4;

        if (nr > 0) {
            float4 acc = make_float4(0.f, 0.f, 0.f, 0.f);
            int ts = 0;
            if (tprev >= 0) {
                const float rp = remprev;
                const float4 h = __ldg(&Hb[(size_t)tprev * H4 + tid]);
                acc.x = rp * h.x; acc.y = rp * h.y;
                acc.z = rp * h.z; acc.w = rp * h.w;
                ts = tprev + 1;
            }
            const int thi = s_ft[nr - 1];       // inclusive end
            int k = 0;
            int t1 = s_ft[0];
            const float* Ab = g_alphas + bT;

            for (int t = ts; t <= thi; t += 4) {
                const int i0 = t, i1 = min(t + 1, thi), i2 = min(t + 2, thi),
                          i3 = min(t + 3, thi);
                const float4 h0 = __ldg(&Hb[(size_t)i0 * H4 + tid]);
                const float4 h1 = __ldg(&Hb[(size_t)i1 * H4 + tid]);
                const float4 h2 = __ldg(&Hb[(size_t)i2 * H4 + tid]);
                const float4 h3 = __ldg(&Hb[(size_t)i3 * H4 + tid]);
                const float a0 = __ldcg(Ab + i0);
                const float a1 = __ldcg(Ab + i1);
                const float a2 = __ldcg(Ab + i2);
                const float a3 = __ldcg(Ab + i3);
                const float4 hv[4] = { h0, h1, h2, h3 };
                const float  av[4] = { a0, a1, a2, a3 };
#pragma unroll
                for (int j = 0; j < 4; j++) {
                    const int tt = t + j;
                    if (tt > thi) break;
                    const float4 h = hv[j];
                    if (tt == t1) {              // fire: close row k
                        const float d = s_dist[k];
                        float4 o;
                        o.x = fmaf(d, h.x, acc.x); o.y = fmaf(d, h.y, acc.y);
                        o.z = fmaf(d, h.z, acc.z); o.w = fmaf(d, h.w, acc.w);
                        Ob[(size_t)(r0 + k) * H4 + tid] = o;
                        const float rm = s_rem[k];
                        acc.x = rm * h.x; acc.y = rm * h.y;
                        acc.z = rm * h.z; acc.w = rm * h.w;
                        ++k;
                        t1 = (k < nr) ? s_ft[k] : -1;
                    } else {                     // interior: accumulate
                        const float a = av[j];
                        acc.x = fmaf(a, h.x, acc.x); acc.y = fmaf(a, h.y, acc.y);
                        acc.z = fmaf(a, h.z, acc.z); acc.w = fmaf(a, h.w, acc.w);
                    }
                }
            }
        }
        // zero-fill padding rows (r >= nf)
        const float4 z4 = make_float4(0.f, 0.f, 0.f, 0.f);
        for (int r = r0 + max(nr, 0); r < rlim; ++r)
            Ob[(size_t)r * H4 + tid] = z4;
    }
}

// ---------------- launch ---------------------------------------------------
extern "C" void kernel_launch(void* const* d_in, const int* in_sizes, int n_in,
                              void* d_out, int out_size)
{
    const float* hidden = (const float*)d_in[0];
    const float* conv_w = (const float*)d_in[1];
    const float* conv_b = (const float*)d_in[2];
    const float* lin_w  = (const float*)d_in[3];
    const float* lin_b  = (const float*)d_in[4];

    float* out = (float*)d_out;

    // Output layout: tuple (cif_output[B,L,H], cif_length[B], fires[B,T])
    const long long fixed = (long long)B_ + (long long)B_ * T_;
    long long rem = (long long)out_size - fixed;
    int L;
    float* out_cif;
    float* out_len;
    float* out_fires;
    if (rem > 0 && rem % ((long long)B_ * H_) == 0) {
        L = (int)(rem / ((long long)B_ * H_));
        out_cif   = out;
        out_len   = out + (size_t)B_ * L * H_;
        out_fires = out_len + B_;
    } else {
        L = (int)((long long)out_size / ((long long)B_ * H_));
        out_cif = out;
        cudaGetSymbolAddress((void**)&out_len, g_dummy_len);
        cudaGetSymbolAddress((void**)&out_fires, g_dummy_fires);
    }

    const int gblocks = (L > 0) ? (L + RPB - 1) / RPB : 0;
    init_kernel<<<1, 32>>>();
    fused_kernel<<<NA + B_ * gblocks, 256>>>(hidden, conv_w, conv_b,
                                             lin_w, lin_b,
                                             out_cif, out_len, out_fires,
                                             L, gblocks);
}